// round 1
// baseline (speedup 1.0000x reference)
#include <cuda_runtime.h>
#include <cuda_bf16.h>
#include <math.h>

// ---------------------------------------------------------------------------
// Problem constants
// ---------------------------------------------------------------------------
#define NPOS   32768          // 32*32*32
#define CCH    128
#define NHEADS 8
#define HD     16
#define KK     27
#define FFN    512

// Scratch (device globals; allocation-free)
__device__ float g_qkv  [NPOS * 384];   // 48 MB
__device__ float g_attno[NPOS * CCH];   // 16 MB
__device__ float g_proj [NPOS * CCH];   // 16 MB
__device__ float g_ffn1 [NPOS * FFN];   // 64 MB
__device__ float g_y    [NPOS * CCH];   // 16 MB
__device__ float g_wt   [128*384 + 128*128 + 128*512 + 512*128];
__device__ float g_stats[512];          // [sum(128) | sumsq(128) | mean(128) | rstd(128)]

#define WT_QKV  0
#define WT_PROJ 49152
#define WT_FFN1 65536
#define WT_FFN2 131072

// ---------------------------------------------------------------------------
// Weight transpose: W[J,K] row-major -> WT[K,J] row-major
// ---------------------------------------------------------------------------
__global__ void prep_weights(const float* __restrict__ wqkv,
                             const float* __restrict__ wproj,
                             const float* __restrict__ wf1,
                             const float* __restrict__ wf2,
                             float* __restrict__ wt)
{
    int i = blockIdx.x * blockDim.x + threadIdx.x;
    if (i >= 196608) return;
    if (i < 49152) {                     // qkv: J=384, K=128
        int k = i / 384, j = i % 384;
        wt[WT_QKV + i] = wqkv[j * 128 + k];
    } else if (i < 65536) {              // proj: 128x128
        int t = i - 49152; int k = t / 128, j = t % 128;
        wt[i] = wproj[j * 128 + k];
    } else if (i < 131072) {             // ffn1: J=512, K=128
        int t = i - 65536; int k = t / 512, j = t % 512;
        wt[i] = wf1[j * 128 + k];
    } else {                             // ffn2: J=128, K=512
        int t = i - 131072; int k = t / 128, j = t % 128;
        wt[i] = wf2[j * 512 + k];
    }
}

// ---------------------------------------------------------------------------
// SGEMM: C[M,J] = act( A[M,K] @ BT[K,J] + bias )  (+ optional normalized resid)
//   ATRANS: A stored as [K,M] (x layout), A[m,k] = A[k*M+m]
//   ANORM : A element normalized per-k: (a - mean[k]) * rstd[k]
//   GELU  : tanh-approx gelu on output
//   RESID : out += (resid[m*J+j] - mean[j]) * rstd[j]
// 128x128 block tile, BK=8, 8x8 per thread, 256 threads.
// ---------------------------------------------------------------------------
template<bool ATRANS, bool ANORM, bool GELU, bool RESID>
__global__ __launch_bounds__(256)
void sgemm(const float* __restrict__ A, const float* __restrict__ BT,
           const float* __restrict__ bias,
           const float* __restrict__ nmean, const float* __restrict__ nrstd,
           const float* __restrict__ resid,
           float* __restrict__ C, int M, int J, int Kd)
{
    constexpr int BM = 128, BN = 128, BK = 8, TM = 8, TN = 8;
    __shared__ float As[BK][BM];
    __shared__ float Bs[BK][BN];

    const int m0 = blockIdx.y * BM;
    const int j0 = blockIdx.x * BN;
    const int tid = threadIdx.x;

    const int aRow = tid / 2;            // ATRANS=false
    const int aCol = (tid % 2) * 4;
    const int atK  = tid / 32;           // ATRANS=true
    const int atM  = (tid % 32) * 4;
    const int bK   = tid / 32;
    const int bJ   = (tid % 32) * 4;
    const int tr   = (tid / 16) * TM;
    const int tc   = (tid % 16) * TN;

    float acc[TM][TN] = {};
    float regM[TM], regN[TN];

    for (int k0 = 0; k0 < Kd; k0 += BK) {
        if (ATRANS) {
            float4 a4 = *reinterpret_cast<const float4*>(&A[(size_t)(k0 + atK) * M + m0 + atM]);
            *reinterpret_cast<float4*>(&As[atK][atM]) = a4;
        } else {
            float4 a4 = *reinterpret_cast<const float4*>(&A[(size_t)(m0 + aRow) * Kd + k0 + aCol]);
            float vals[4] = {a4.x, a4.y, a4.z, a4.w};
            #pragma unroll
            for (int i = 0; i < 4; i++) {
                float v = vals[i];
                if (ANORM) { int kk = k0 + aCol + i; v = (v - nmean[kk]) * nrstd[kk]; }
                As[aCol + i][aRow] = v;
            }
        }
        float4 b4 = *reinterpret_cast<const float4*>(&BT[(size_t)(k0 + bK) * J + j0 + bJ]);
        *reinterpret_cast<float4*>(&Bs[bK][bJ]) = b4;
        __syncthreads();

        #pragma unroll
        for (int kk = 0; kk < BK; kk++) {
            #pragma unroll
            for (int i = 0; i < TM; i++) regM[i] = As[kk][tr + i];
            #pragma unroll
            for (int j = 0; j < TN; j++) regN[j] = Bs[kk][tc + j];
            #pragma unroll
            for (int i = 0; i < TM; i++)
                #pragma unroll
                for (int j = 0; j < TN; j++)
                    acc[i][j] += regM[i] * regN[j];
        }
        __syncthreads();
    }

    #pragma unroll
    for (int i = 0; i < TM; i++) {
        int m = m0 + tr + i;
        #pragma unroll
        for (int j = 0; j < TN; j += 4) {
            float4 o;
            float* op = &o.x;
            #pragma unroll
            for (int q = 0; q < 4; q++) {
                int jj = j0 + tc + j + q;
                float v = acc[i][j + q] + bias[jj];
                if (GELU) {
                    float xx = v;
                    float t = tanhf(0.7978845608028654f * (xx + 0.044715f * xx * xx * xx));
                    v = 0.5f * xx * (1.0f + t);
                }
                if (RESID) {
                    float r = resid[(size_t)m * J + jj];
                    v += (r - nmean[jj]) * nrstd[jj];
                }
                op[q] = v;
            }
            *reinterpret_cast<float4*>(&C[(size_t)m * J + j0 + tc + j]) = o;
        }
    }
}

// ---------------------------------------------------------------------------
// Neighborhood attention: one block = 4x4x4 position tile x one head.
// K/V staged for the 6x6x6 covering region in shared memory.
// ---------------------------------------------------------------------------
__global__ __launch_bounds__(64)
void nattn(const float* __restrict__ qkv, const float* __restrict__ rpb,
           float* __restrict__ out)
{
    __shared__ float Kt[216 * 16];
    __shared__ float Vt[216 * 16];
    __shared__ float Bsh[125];

    const int head = blockIdx.y;
    const int tile = blockIdx.x;
    const int th = tile >> 6, tw = (tile >> 3) & 7, tz = tile & 7;
    const int h0 = th * 4, w0 = tw * 4, z0 = tz * 4;
    const int rbh = h0 - 1, rbw = w0 - 1, rbz = z0 - 1;
    const int tid = threadIdx.x;

    // Stage K/V (float4 granularity: 216 positions x 4 float4)
    for (int i = tid; i < 216 * 4; i += 64) {
        int p  = i >> 2;
        int d4 = (i & 3) * 4;
        int pz = p % 6, pw = (p / 6) % 6, ph = p / 36;
        int gh = min(max(rbh + ph, 0), 31);
        int gw = min(max(rbw + pw, 0), 31);
        int gz = min(max(rbz + pz, 0), 31);
        int n = (gh * 32 + gw) * 32 + gz;
        const float* base = qkv + (size_t)n * 384 + head * 16 + d4;
        *reinterpret_cast<float4*>(&Kt[p * 16 + d4]) = *reinterpret_cast<const float4*>(base + 128);
        *reinterpret_cast<float4*>(&Vt[p * 16 + d4]) = *reinterpret_cast<const float4*>(base + 256);
    }
    for (int i = tid; i < 125; i += 64) Bsh[i] = rpb[head * 125 + i];
    __syncthreads();

    // Each thread: one query position
    const int lz = tid & 3, lw = (tid >> 2) & 3, lh = tid >> 4;
    const int qh = h0 + lh, qw = w0 + lw, qz = z0 + lz;
    const int n = (qh * 32 + qw) * 32 + qz;

    float q[16];
    {
        const float4* qp = reinterpret_cast<const float4*>(qkv + (size_t)n * 384 + head * 16);
        #pragma unroll
        for (int d4 = 0; d4 < 4; d4++) {
            float4 v = qp[d4];
            q[d4*4+0] = v.x * 0.25f; q[d4*4+1] = v.y * 0.25f;
            q[d4*4+2] = v.z * 0.25f; q[d4*4+3] = v.w * 0.25f;
        }
    }

    const int sh = min(max(qh - 1, 0), 29);
    const int sw = min(max(qw - 1, 0), 29);
    const int sz = min(max(qz - 1, 0), 29);

    float logits[27];
    float mx = -1e30f;
    #pragma unroll
    for (int ii = 0; ii < 27; ii++) {
        int iz = ii % 3, iw = (ii / 3) % 3, ih = ii / 9;
        int nh = sh + ih, nw_ = sw + iw, nz = sz + iz;
        int sp = ((nh - rbh) * 6 + (nw_ - rbw)) * 6 + (nz - rbz);
        const float4* kp = reinterpret_cast<const float4*>(&Kt[sp * 16]);
        float dot = 0.f;
        #pragma unroll
        for (int d4 = 0; d4 < 4; d4++) {
            float4 kv = kp[d4];
            dot += q[d4*4+0]*kv.x + q[d4*4+1]*kv.y + q[d4*4+2]*kv.z + q[d4*4+3]*kv.w;
        }
        int rh = nh - qh + 2, rw = nw_ - qw + 2, rz = nz - qz + 2;
        dot += Bsh[(rh * 5 + rw) * 5 + rz];
        logits[ii] = dot;
        mx = fmaxf(mx, dot);
    }
    float s = 0.f;
    #pragma unroll
    for (int ii = 0; ii < 27; ii++) { logits[ii] = __expf(logits[ii] - mx); s += logits[ii]; }
    const float inv = 1.0f / s;

    float o[16] = {};
    #pragma unroll
    for (int ii = 0; ii < 27; ii++) {
        int iz = ii % 3, iw = (ii / 3) % 3, ih = ii / 9;
        int sp = ((sh + ih - rbh) * 6 + (sw + iw - rbw)) * 6 + (sz + iz - rbz);
        const float4* vp = reinterpret_cast<const float4*>(&Vt[sp * 16]);
        float w = logits[ii];
        #pragma unroll
        for (int d4 = 0; d4 < 4; d4++) {
            float4 vv = vp[d4];
            o[d4*4+0] += w * vv.x; o[d4*4+1] += w * vv.y;
            o[d4*4+2] += w * vv.z; o[d4*4+3] += w * vv.w;
        }
    }
    float4* op = reinterpret_cast<float4*>(out + (size_t)n * 128 + head * 16);
    #pragma unroll
    for (int d4 = 0; d4 < 4; d4++) {
        float4 v;
        v.x = o[d4*4+0]*inv; v.y = o[d4*4+1]*inv;
        v.z = o[d4*4+2]*inv; v.w = o[d4*4+3]*inv;
        op[d4] = v;
    }
}

// ---------------------------------------------------------------------------
// Instance-norm statistics over N per channel (y is [N,128] row-major)
// ---------------------------------------------------------------------------
__global__ void zero_stats(float* s) { s[threadIdx.x] = 0.f; }   // 256 threads

__global__ __launch_bounds__(128)
void stats_kernel(const float* __restrict__ y, float* __restrict__ sum,
                  float* __restrict__ sumsq)
{
    const int c = threadIdx.x;
    const int r0 = blockIdx.x * 256;
    float s = 0.f, s2 = 0.f;
    #pragma unroll 4
    for (int r = 0; r < 256; r++) {
        float v = y[(size_t)(r0 + r) * 128 + c];
        s += v; s2 += v * v;
    }
    atomicAdd(&sum[c], s);
    atomicAdd(&sumsq[c], s2);
}

__global__ void finalize_stats(const float* sum, const float* sumsq,
                               float* mean, float* rstd)
{
    int c = threadIdx.x;
    float m = sum[c] * (1.0f / NPOS);
    mean[c] = m;
    rstd[c] = rsqrtf(sumsq[c] * (1.0f / NPOS) - m * m + 1e-5f);
}

// ---------------------------------------------------------------------------
// Final: normalize + transpose [N,128] -> [128,N]
// ---------------------------------------------------------------------------
__global__ __launch_bounds__(256)
void transnorm(const float* __restrict__ y, const float* __restrict__ mean,
               const float* __restrict__ rstd, float* __restrict__ out)
{
    __shared__ float tile[32][33];
    const int n0 = blockIdx.x * 32;
    const int c0 = blockIdx.y * 32;
    const int tx = threadIdx.x, ty = threadIdx.y;
    for (int i = ty; i < 32; i += 8)
        tile[i][tx] = y[(size_t)(n0 + i) * 128 + c0 + tx];
    __syncthreads();
    for (int i = ty; i < 32; i += 8) {
        int c = c0 + i;
        out[(size_t)c * NPOS + n0 + tx] = (tile[tx][i] - mean[c]) * rstd[c];
    }
}

// ---------------------------------------------------------------------------
// Launch
// ---------------------------------------------------------------------------
extern "C" void kernel_launch(void* const* d_in, const int* in_sizes, int n_in,
                              void* d_out, int out_size)
{
    const float* x      = (const float*)d_in[0];
    const float* w_qkv  = (const float*)d_in[1];
    const float* b_qkv  = (const float*)d_in[2];
    const float* rpb    = (const float*)d_in[3];
    const float* w_proj = (const float*)d_in[4];
    const float* b_proj = (const float*)d_in[5];
    const float* w_ffn1 = (const float*)d_in[6];
    const float* b_ffn1 = (const float*)d_in[7];
    const float* w_ffn2 = (const float*)d_in[8];
    const float* b_ffn2 = (const float*)d_in[9];
    float* out = (float*)d_out;

    float *qkv, *attno, *proj, *ffn1, *y, *wt, *st;
    cudaGetSymbolAddress((void**)&qkv,   g_qkv);
    cudaGetSymbolAddress((void**)&attno, g_attno);
    cudaGetSymbolAddress((void**)&proj,  g_proj);
    cudaGetSymbolAddress((void**)&ffn1,  g_ffn1);
    cudaGetSymbolAddress((void**)&y,     g_y);
    cudaGetSymbolAddress((void**)&wt,    g_wt);
    cudaGetSymbolAddress((void**)&st,    g_stats);

    // 1. transpose weights
    prep_weights<<<768, 256>>>(w_qkv, w_proj, w_ffn1, w_ffn2, wt);

    // 2. QKV GEMM: A = x^T (x stored [128, N])
    sgemm<true, false, false, false><<<dim3(3, 256), 256>>>(
        x, wt + WT_QKV, b_qkv, nullptr, nullptr, nullptr, qkv, NPOS, 384, 128);

    // 3. neighborhood attention
    nattn<<<dim3(512, NHEADS), 64>>>(qkv, rpb, attno);

    // 4. proj GEMM
    sgemm<false, false, false, false><<<dim3(1, 256), 256>>>(
        attno, wt + WT_PROJ, b_proj, nullptr, nullptr, nullptr, proj, NPOS, 128, 128);

    // 5. instance norm #1 stats (of proj)
    zero_stats<<<1, 256>>>(st);
    stats_kernel<<<128, 128>>>(proj, st, st + 128);
    finalize_stats<<<1, 128>>>(st, st + 128, st + 256, st + 384);

    // 6. FFN1 (A = normalized proj) + gelu
    sgemm<false, true, true, false><<<dim3(4, 256), 256>>>(
        proj, wt + WT_FFN1, b_ffn1, st + 256, st + 384, nullptr, ffn1, NPOS, 512, 128);

    // 7. FFN2 + residual (residual = normalized proj)
    sgemm<false, false, false, true><<<dim3(1, 256), 256>>>(
        ffn1, wt + WT_FFN2, b_ffn2, st + 256, st + 384, proj, y, NPOS, 128, 512);

    // 8. instance norm #2 stats (of y)
    zero_stats<<<1, 256>>>(st);
    stats_kernel<<<128, 128>>>(y, st, st + 128);
    finalize_stats<<<1, 128>>>(st, st + 128, st + 256, st + 384);

    // 9. normalize + transpose to [C, N]
    transnorm<<<dim3(1024, 4), dim3(32, 8)>>>(y, st + 256, st + 384, out);
}

// round 2
// speedup vs baseline: 1.8421x; 1.8421x over previous
#include <cuda_runtime.h>
#include <cuda_bf16.h>
#include <math.h>

// ---------------------------------------------------------------------------
// Problem constants
// ---------------------------------------------------------------------------
#define NPOS   32768          // 32*32*32
#define CCH    128
#define NHEADS 8
#define HD     16
#define KK     27
#define FFN    512

// Scratch (device globals; allocation-free)
__device__ float g_qkv  [NPOS * 384];   // 48 MB
__device__ float g_attno[NPOS * CCH];   // 16 MB
__device__ float g_proj [NPOS * CCH];   // 16 MB
__device__ float g_ffn1 [NPOS * FFN];   // 64 MB
__device__ float g_y    [NPOS * CCH];   // 16 MB
__device__ float g_wt   [128*384 + 128*128 + 128*512 + 512*128];
__device__ float g_stats[512];          // [sum(128) | sumsq(128) | mean(128) | rstd(128)]

#define WT_QKV  0
#define WT_PROJ 49152
#define WT_FFN1 65536
#define WT_FFN2 131072

typedef unsigned long long u64;

__device__ __forceinline__ u64 pack2same(float a) {
    u64 r; asm("mov.b64 %0, {%1, %1};" : "=l"(r) : "f"(a)); return r;
}
__device__ __forceinline__ void ffma2(u64& d, u64 a, u64 b) {
    asm("fma.rn.f32x2 %0, %1, %2, %0;" : "+l"(d) : "l"(a), "l"(b));
}
__device__ __forceinline__ float2 unpack2(u64 v) {
    float2 r; asm("mov.b64 {%0, %1}, %2;" : "=f"(r.x), "=f"(r.y) : "l"(v)); return r;
}
__device__ __forceinline__ float fast_tanh(float x) {
    float r; asm("tanh.approx.f32 %0, %1;" : "=f"(r) : "f"(x)); return r;
}

// ---------------------------------------------------------------------------
// Weight transpose: W[J,K] row-major -> WT[K,J] row-major
// ---------------------------------------------------------------------------
__global__ void prep_weights(const float* __restrict__ wqkv,
                             const float* __restrict__ wproj,
                             const float* __restrict__ wf1,
                             const float* __restrict__ wf2,
                             float* __restrict__ wt)
{
    int i = blockIdx.x * blockDim.x + threadIdx.x;
    if (i >= 196608) return;
    if (i < 49152) {                     // qkv: J=384, K=128
        int k = i / 384, j = i % 384;
        wt[WT_QKV + i] = wqkv[j * 128 + k];
    } else if (i < 65536) {              // proj: 128x128
        int t = i - 49152; int k = t / 128, j = t % 128;
        wt[i] = wproj[j * 128 + k];
    } else if (i < 131072) {             // ffn1: J=512, K=128
        int t = i - 65536; int k = t / 512, j = t % 512;
        wt[i] = wf1[j * 128 + k];
    } else {                             // ffn2: J=128, K=512
        int t = i - 131072; int k = t / 128, j = t % 128;
        wt[i] = wf2[j * 512 + k];
    }
}

// ---------------------------------------------------------------------------
// SGEMM with packed f32x2 FMA inner loop.
// C[M,J] = act( A[M,K] @ BT[K,J] + bias )  (+ optional normalized resid)
//   ATRANS: A stored as [K,M] (x layout)
//   ANORM : A element normalized per-k: (a - mean[k]) * rstd[k]
//   GELU  : tanh-approx gelu on output
//   RESID : out += (resid[m*J+j] - mean[j]) * rstd[j]
// 128x128 block tile, BK=8, 8x8 per thread, 256 threads.
// ---------------------------------------------------------------------------
template<bool ATRANS, bool ANORM, bool GELU, bool RESID>
__global__ __launch_bounds__(256)
void sgemm(const float* __restrict__ A, const float* __restrict__ BT,
           const float* __restrict__ bias,
           const float* __restrict__ nmean, const float* __restrict__ nrstd,
           const float* __restrict__ resid,
           float* __restrict__ C, int M, int J, int Kd)
{
    constexpr int BM = 128, BN = 128, BK = 8, TM = 8, TN = 8;
    __shared__ float As[BK][BM];
    __shared__ float Bs[BK][BN];

    const int m0 = blockIdx.y * BM;
    const int j0 = blockIdx.x * BN;
    const int tid = threadIdx.x;

    const int aRow = tid / 2;            // ATRANS=false
    const int aCol = (tid % 2) * 4;
    const int atK  = tid / 32;           // ATRANS=true
    const int atM  = (tid % 32) * 4;
    const int bK   = tid / 32;
    const int bJ   = (tid % 32) * 4;
    const int tr   = (tid / 16) * TM;
    const int tc   = (tid % 16) * TN;

    u64 acc[TM][TN / 2] = {};
    float regM[TM];
    u64 regN2[TN / 2];

    for (int k0 = 0; k0 < Kd; k0 += BK) {
        if (ATRANS) {
            float4 a4 = *reinterpret_cast<const float4*>(&A[(size_t)(k0 + atK) * M + m0 + atM]);
            *reinterpret_cast<float4*>(&As[atK][atM]) = a4;
        } else {
            float4 a4 = *reinterpret_cast<const float4*>(&A[(size_t)(m0 + aRow) * Kd + k0 + aCol]);
            float vals[4] = {a4.x, a4.y, a4.z, a4.w};
            #pragma unroll
            for (int i = 0; i < 4; i++) {
                float v = vals[i];
                if (ANORM) { int kk = k0 + aCol + i; v = (v - nmean[kk]) * nrstd[kk]; }
                As[aCol + i][aRow] = v;
            }
        }
        float4 b4 = *reinterpret_cast<const float4*>(&BT[(size_t)(k0 + bK) * J + j0 + bJ]);
        *reinterpret_cast<float4*>(&Bs[bK][bJ]) = b4;
        __syncthreads();

        #pragma unroll
        for (int kk = 0; kk < BK; kk++) {
            #pragma unroll
            for (int i = 0; i < TM; i += 4) {
                float4 m4 = *reinterpret_cast<const float4*>(&As[kk][tr + i]);
                regM[i+0] = m4.x; regM[i+1] = m4.y; regM[i+2] = m4.z; regM[i+3] = m4.w;
            }
            #pragma unroll
            for (int j = 0; j < TN / 2; j++)
                regN2[j] = *reinterpret_cast<const u64*>(&Bs[kk][tc + 2*j]);
            #pragma unroll
            for (int i = 0; i < TM; i++) {
                u64 m2 = pack2same(regM[i]);
                #pragma unroll
                for (int j = 0; j < TN / 2; j++)
                    ffma2(acc[i][j], m2, regN2[j]);
            }
        }
        __syncthreads();
    }

    #pragma unroll
    for (int i = 0; i < TM; i++) {
        int m = m0 + tr + i;
        #pragma unroll
        for (int j = 0; j < TN; j += 4) {
            float2 p0 = unpack2(acc[i][j/2]);
            float2 p1 = unpack2(acc[i][j/2 + 1]);
            float vals[4] = {p0.x, p0.y, p1.x, p1.y};
            float4 o;
            float* op = &o.x;
            #pragma unroll
            for (int q = 0; q < 4; q++) {
                int jj = j0 + tc + j + q;
                float v = vals[q] + bias[jj];
                if (GELU) {
                    float xx = v;
                    float t = fast_tanh(0.7978845608028654f * (xx + 0.044715f * xx * xx * xx));
                    v = 0.5f * xx * (1.0f + t);
                }
                if (RESID) {
                    float r = resid[(size_t)m * J + jj];
                    v += (r - nmean[jj]) * nrstd[jj];
                }
                op[q] = v;
            }
            *reinterpret_cast<float4*>(&C[(size_t)m * J + j0 + tc + j]) = o;
        }
    }
}

// ---------------------------------------------------------------------------
// Neighborhood attention: one block = 4x4x4 position tile x one head.
// K/V staged for the 6x6x6 covering region in shared memory.
// ---------------------------------------------------------------------------
__global__ __launch_bounds__(64)
void nattn(const float* __restrict__ qkv, const float* __restrict__ rpb,
           float* __restrict__ out)
{
    __shared__ float Kt[216 * 16];
    __shared__ float Vt[216 * 16];
    __shared__ float Bsh[125];

    const int head = blockIdx.y;
    const int tile = blockIdx.x;
    const int th = tile >> 6, tw = (tile >> 3) & 7, tz = tile & 7;
    const int h0 = th * 4, w0 = tw * 4, z0 = tz * 4;
    const int rbh = h0 - 1, rbw = w0 - 1, rbz = z0 - 1;
    const int tid = threadIdx.x;

    // Stage K/V (float4 granularity: 216 positions x 4 float4)
    for (int i = tid; i < 216 * 4; i += 64) {
        int p  = i >> 2;
        int d4 = (i & 3) * 4;
        int pz = p % 6, pw = (p / 6) % 6, ph = p / 36;
        int gh = min(max(rbh + ph, 0), 31);
        int gw = min(max(rbw + pw, 0), 31);
        int gz = min(max(rbz + pz, 0), 31);
        int n = (gh * 32 + gw) * 32 + gz;
        const float* base = qkv + (size_t)n * 384 + head * 16 + d4;
        *reinterpret_cast<float4*>(&Kt[p * 16 + d4]) = *reinterpret_cast<const float4*>(base + 128);
        *reinterpret_cast<float4*>(&Vt[p * 16 + d4]) = *reinterpret_cast<const float4*>(base + 256);
    }
    for (int i = tid; i < 125; i += 64) Bsh[i] = rpb[head * 125 + i];
    __syncthreads();

    // Each thread: one query position
    const int lz = tid & 3, lw = (tid >> 2) & 3, lh = tid >> 4;
    const int qh = h0 + lh, qw = w0 + lw, qz = z0 + lz;
    const int n = (qh * 32 + qw) * 32 + qz;

    float q[16];
    {
        const float4* qp = reinterpret_cast<const float4*>(qkv + (size_t)n * 384 + head * 16);
        #pragma unroll
        for (int d4 = 0; d4 < 4; d4++) {
            float4 v = qp[d4];
            q[d4*4+0] = v.x * 0.25f; q[d4*4+1] = v.y * 0.25f;
            q[d4*4+2] = v.z * 0.25f; q[d4*4+3] = v.w * 0.25f;
        }
    }

    const int sh = min(max(qh - 1, 0), 29);
    const int sw = min(max(qw - 1, 0), 29);
    const int sz = min(max(qz - 1, 0), 29);

    float logits[27];
    float mx = -1e30f;
    #pragma unroll
    for (int ii = 0; ii < 27; ii++) {
        int iz = ii % 3, iw = (ii / 3) % 3, ih = ii / 9;
        int nh = sh + ih, nw_ = sw + iw, nz = sz + iz;
        int sp = ((nh - rbh) * 6 + (nw_ - rbw)) * 6 + (nz - rbz);
        const float4* kp = reinterpret_cast<const float4*>(&Kt[sp * 16]);
        float dot = 0.f;
        #pragma unroll
        for (int d4 = 0; d4 < 4; d4++) {
            float4 kv = kp[d4];
            dot += q[d4*4+0]*kv.x + q[d4*4+1]*kv.y + q[d4*4+2]*kv.z + q[d4*4+3]*kv.w;
        }
        int rh = nh - qh + 2, rw = nw_ - qw + 2, rz = nz - qz + 2;
        dot += Bsh[(rh * 5 + rw) * 5 + rz];
        logits[ii] = dot;
        mx = fmaxf(mx, dot);
    }
    float s = 0.f;
    #pragma unroll
    for (int ii = 0; ii < 27; ii++) { logits[ii] = __expf(logits[ii] - mx); s += logits[ii]; }
    const float inv = 1.0f / s;

    float o[16] = {};
    #pragma unroll
    for (int ii = 0; ii < 27; ii++) {
        int iz = ii % 3, iw = (ii / 3) % 3, ih = ii / 9;
        int sp = ((sh + ih - rbh) * 6 + (sw + iw - rbw)) * 6 + (sz + iz - rbz);
        const float4* vp = reinterpret_cast<const float4*>(&Vt[sp * 16]);
        float w = logits[ii];
        #pragma unroll
        for (int d4 = 0; d4 < 4; d4++) {
            float4 vv = vp[d4];
            o[d4*4+0] += w * vv.x; o[d4*4+1] += w * vv.y;
            o[d4*4+2] += w * vv.z; o[d4*4+3] += w * vv.w;
        }
    }
    float4* op = reinterpret_cast<float4*>(out + (size_t)n * 128 + head * 16);
    #pragma unroll
    for (int d4 = 0; d4 < 4; d4++) {
        float4 v;
        v.x = o[d4*4+0]*inv; v.y = o[d4*4+1]*inv;
        v.z = o[d4*4+2]*inv; v.w = o[d4*4+3]*inv;
        op[d4] = v;
    }
}

// ---------------------------------------------------------------------------
// Instance-norm statistics over N per channel (y is [N,128] row-major)
// ---------------------------------------------------------------------------
__global__ void zero_stats(float* s) { s[threadIdx.x] = 0.f; }   // 256 threads

__global__ __launch_bounds__(128)
void stats_kernel(const float* __restrict__ y, float* __restrict__ sum,
                  float* __restrict__ sumsq)
{
    const int c = threadIdx.x;
    const int r0 = blockIdx.x * 256;
    float s = 0.f, s2 = 0.f;
    #pragma unroll 4
    for (int r = 0; r < 256; r++) {
        float v = y[(size_t)(r0 + r) * 128 + c];
        s += v; s2 += v * v;
    }
    atomicAdd(&sum[c], s);
    atomicAdd(&sumsq[c], s2);
}

__global__ void finalize_stats(const float* sum, const float* sumsq,
                               float* mean, float* rstd)
{
    int c = threadIdx.x;
    float m = sum[c] * (1.0f / NPOS);
    mean[c] = m;
    rstd[c] = rsqrtf(sumsq[c] * (1.0f / NPOS) - m * m + 1e-5f);
}

// ---------------------------------------------------------------------------
// Final: normalize + transpose [N,128] -> [128,N]
// ---------------------------------------------------------------------------
__global__ __launch_bounds__(256)
void transnorm(const float* __restrict__ y, const float* __restrict__ mean,
               const float* __restrict__ rstd, float* __restrict__ out)
{
    __shared__ float tile[32][33];
    const int n0 = blockIdx.x * 32;
    const int c0 = blockIdx.y * 32;
    const int tx = threadIdx.x, ty = threadIdx.y;
    for (int i = ty; i < 32; i += 8)
        tile[i][tx] = y[(size_t)(n0 + i) * 128 + c0 + tx];
    __syncthreads();
    for (int i = ty; i < 32; i += 8) {
        int c = c0 + i;
        out[(size_t)c * NPOS + n0 + tx] = (tile[tx][i] - mean[c]) * rstd[c];
    }
}

// ---------------------------------------------------------------------------
// Launch
// ---------------------------------------------------------------------------
extern "C" void kernel_launch(void* const* d_in, const int* in_sizes, int n_in,
                              void* d_out, int out_size)
{
    const float* x      = (const float*)d_in[0];
    const float* w_qkv  = (const float*)d_in[1];
    const float* b_qkv  = (const float*)d_in[2];
    const float* rpb    = (const float*)d_in[3];
    const float* w_proj = (const float*)d_in[4];
    const float* b_proj = (const float*)d_in[5];
    const float* w_ffn1 = (const float*)d_in[6];
    const float* b_ffn1 = (const float*)d_in[7];
    const float* w_ffn2 = (const float*)d_in[8];
    const float* b_ffn2 = (const float*)d_in[9];
    float* out = (float*)d_out;

    float *qkv, *attno, *proj, *ffn1, *y, *wt, *st;
    cudaGetSymbolAddress((void**)&qkv,   g_qkv);
    cudaGetSymbolAddress((void**)&attno, g_attno);
    cudaGetSymbolAddress((void**)&proj,  g_proj);
    cudaGetSymbolAddress((void**)&ffn1,  g_ffn1);
    cudaGetSymbolAddress((void**)&y,     g_y);
    cudaGetSymbolAddress((void**)&wt,    g_wt);
    cudaGetSymbolAddress((void**)&st,    g_stats);

    // 1. transpose weights
    prep_weights<<<768, 256>>>(w_qkv, w_proj, w_ffn1, w_ffn2, wt);

    // 2. QKV GEMM: A = x^T (x stored [128, N])
    sgemm<true, false, false, false><<<dim3(3, 256), 256>>>(
        x, wt + WT_QKV, b_qkv, nullptr, nullptr, nullptr, qkv, NPOS, 384, 128);

    // 3. neighborhood attention
    nattn<<<dim3(512, NHEADS), 64>>>(qkv, rpb, attno);

    // 4. proj GEMM
    sgemm<false, false, false, false><<<dim3(1, 256), 256>>>(
        attno, wt + WT_PROJ, b_proj, nullptr, nullptr, nullptr, proj, NPOS, 128, 128);

    // 5. instance norm #1 stats (of proj)
    zero_stats<<<1, 256>>>(st);
    stats_kernel<<<128, 128>>>(proj, st, st + 128);
    finalize_stats<<<1, 128>>>(st, st + 128, st + 256, st + 384);

    // 6. FFN1 (A = normalized proj) + gelu
    sgemm<false, true, true, false><<<dim3(4, 256), 256>>>(
        proj, wt + WT_FFN1, b_ffn1, st + 256, st + 384, nullptr, ffn1, NPOS, 512, 128);

    // 7. FFN2 + residual (residual = normalized proj)
    sgemm<false, false, false, true><<<dim3(1, 256), 256>>>(
        ffn1, wt + WT_FFN2, b_ffn2, st + 256, st + 384, proj, y, NPOS, 128, 512);

    // 8. instance norm #2 stats (of y)
    zero_stats<<<1, 256>>>(st);
    stats_kernel<<<128, 128>>>(y, st, st + 128);
    finalize_stats<<<1, 128>>>(st, st + 128, st + 256, st + 384);

    // 9. normalize + transpose to [C, N]
    transnorm<<<dim3(1024, 4), dim3(32, 8)>>>(y, st + 256, st + 384, out);
}

// round 4
// speedup vs baseline: 2.4871x; 1.3502x over previous
#include <cuda_runtime.h>
#include <cuda_bf16.h>
#include <math.h>
#include <stdint.h>

// ---------------------------------------------------------------------------
// Problem constants
// ---------------------------------------------------------------------------
#define NPOS   32768          // 32*32*32
#define CCH    128
#define NHEADS 8
#define FFN    512

// Scratch (device globals; allocation-free)
__device__ float g_qkv  [NPOS * 384];   // 48 MB
__device__ float g_attno[NPOS * CCH];   // 16 MB
__device__ float g_proj [NPOS * CCH];   // 16 MB
__device__ float g_ffn1 [NPOS * FFN];   // 64 MB
__device__ float g_y    [NPOS * CCH];   // 16 MB
__device__ float g_stats[512];          // [sum | sumsq | mean | rstd]

// ---------------------------------------------------------------------------
// PTX helpers (family-portable: ldmatrix + mma.sync, sm_80+ baseline)
// ---------------------------------------------------------------------------
__device__ __forceinline__ uint32_t smem_u32(const void* p) {
    uint32_t a;
    asm("{ .reg .u64 t; cvta.to.shared.u64 t, %1; cvt.u32.u64 %0, t; }" : "=r"(a) : "l"(p));
    return a;
}
__device__ __forceinline__ float fast_tanh(float x) {
    float r; asm("tanh.approx.f32 %0, %1;" : "=f"(r) : "f"(x)); return r;
}
__device__ __forceinline__ void ldsm_x4(uint32_t* r, uint32_t addr) {
    asm volatile("ldmatrix.sync.aligned.m8n8.x4.shared.b16 {%0,%1,%2,%3}, [%4];"
        : "=r"(r[0]), "=r"(r[1]), "=r"(r[2]), "=r"(r[3]) : "r"(addr));
}
__device__ __forceinline__ void ldsm_x4_t(uint32_t* r, uint32_t addr) {
    asm volatile("ldmatrix.sync.aligned.m8n8.x4.trans.shared.b16 {%0,%1,%2,%3}, [%4];"
        : "=r"(r[0]), "=r"(r[1]), "=r"(r[2]), "=r"(r[3]) : "r"(addr));
}
__device__ __forceinline__ void mma16816(float* c, const uint32_t* a, const uint32_t* b) {
    asm volatile("mma.sync.aligned.m16n8k16.row.col.f32.bf16.bf16.f32 "
        "{%0,%1,%2,%3}, {%4,%5,%6,%7}, {%8,%9}, {%0,%1,%2,%3};"
        : "+f"(c[0]), "+f"(c[1]), "+f"(c[2]), "+f"(c[3])
        : "r"(a[0]), "r"(a[1]), "r"(a[2]), "r"(a[3]), "r"(b[0]), "r"(b[1]));
}

// ---------------------------------------------------------------------------
// Split-bf16 GEMM on mma.sync tensor cores.
// C[M,J] = act( A[M,Kd] @ W[J,Kd]^T + bias )  (+ optional normalized resid)
//   ATRANS: A stored as [Kd, M] (x layout)
//   ANORM : A normalized per-k: (a - mean[k]) * rstd[k]
//   GELU  : tanh-approx gelu on output
//   RESID : out += (resid[m*J+j] - mean[j]) * rstd[j]
// Block = 128x128 output tile; BK=32 chunks; 256 threads = 8 warps (2x4),
// 64x32 tile per warp. fp32 accurate via hi/lo bf16 split (3 mma products).
// ---------------------------------------------------------------------------
#define APAD 8
#define BPAD 8

template<bool ATRANS, bool ANORM, bool GELU, bool RESID>
__global__ __launch_bounds__(256)
void mmagemm(const float* __restrict__ A, const float* __restrict__ W,
             const float* __restrict__ bias,
             const float* __restrict__ nmean, const float* __restrict__ nrstd,
             const float* __restrict__ resid,
             float* __restrict__ C, int M, int J, int Kd)
{
    __shared__ __nv_bfloat16 As_h[128][32 + APAD];
    __shared__ __nv_bfloat16 As_l[128][32 + APAD];
    __shared__ __nv_bfloat16 Bs_h[32][128 + BPAD];
    __shared__ __nv_bfloat16 Bs_l[32][128 + BPAD];

    const int tid  = threadIdx.x;
    const int wid  = tid >> 5;
    const int lane = tid & 31;
    const int m0 = blockIdx.y * 128;
    const int j0 = blockIdx.x * 128;
    const int mw = wid >> 2;       // 0-1
    const int nw = wid & 3;        // 0-3

    const uint32_t sAh = smem_u32(As_h), sAl = smem_u32(As_l);
    const uint32_t sBh = smem_u32(Bs_h), sBl = smem_u32(Bs_l);

    float acc[4][4][4] = {};       // [mt][nt][frag]

    const int nchunk = Kd >> 5;
    for (int kc = 0; kc < nchunk; kc++) {
        const int k0 = kc << 5;

        // ---- fill A hi/lo ----
        if (ATRANS) {
            #pragma unroll
            for (int idx = tid; idx < 1024; idx += 256) {
                int k  = idx >> 5;
                int m4 = (idx & 31) << 2;
                float4 v = *reinterpret_cast<const float4*>(&A[(size_t)(k0 + k) * M + m0 + m4]);
                float vals[4] = {v.x, v.y, v.z, v.w};
                #pragma unroll
                for (int e = 0; e < 4; e++) {
                    __nv_bfloat16 h = __float2bfloat16(vals[e]);
                    __nv_bfloat16 l = __float2bfloat16(vals[e] - __bfloat162float(h));
                    As_h[m4 + e][k] = h;
                    As_l[m4 + e][k] = l;
                }
            }
        } else {
            #pragma unroll
            for (int idx = tid; idx < 1024; idx += 256) {
                int r  = idx >> 3;
                int c4 = (idx & 7) << 2;
                float4 v = *reinterpret_cast<const float4*>(&A[(size_t)(m0 + r) * Kd + k0 + c4]);
                float vals[4] = {v.x, v.y, v.z, v.w};
                if (ANORM) {
                    #pragma unroll
                    for (int e = 0; e < 4; e++) {
                        int kk = k0 + c4 + e;
                        vals[e] = (vals[e] - nmean[kk]) * nrstd[kk];
                    }
                }
                #pragma unroll
                for (int e = 0; e < 2; e++) {
                    __nv_bfloat16 h0 = __float2bfloat16(vals[2*e]);
                    __nv_bfloat16 h1 = __float2bfloat16(vals[2*e+1]);
                    __nv_bfloat16 l0 = __float2bfloat16(vals[2*e]   - __bfloat162float(h0));
                    __nv_bfloat16 l1 = __float2bfloat16(vals[2*e+1] - __bfloat162float(h1));
                    *reinterpret_cast<__nv_bfloat162*>(&As_h[r][c4 + 2*e]) = __nv_bfloat162(h0, h1);
                    *reinterpret_cast<__nv_bfloat162*>(&As_l[r][c4 + 2*e]) = __nv_bfloat162(l0, l1);
                }
            }
        }
        // ---- fill B hi/lo (W is [J, Kd] row-major; store k-major) ----
        #pragma unroll
        for (int idx = tid; idx < 1024; idx += 256) {
            int n  = idx >> 3;
            int kg = (idx & 7) << 2;
            float4 v = *reinterpret_cast<const float4*>(&W[(size_t)(j0 + n) * Kd + k0 + kg]);
            float vals[4] = {v.x, v.y, v.z, v.w};
            #pragma unroll
            for (int e = 0; e < 4; e++) {
                __nv_bfloat16 h = __float2bfloat16(vals[e]);
                __nv_bfloat16 l = __float2bfloat16(vals[e] - __bfloat162float(h));
                Bs_h[kg + e][n] = h;
                Bs_l[kg + e][n] = l;
            }
        }
        __syncthreads();

        // ---- 2 k-steps of 16 ----
        #pragma unroll
        for (int ks = 0; ks < 2; ks++) {
            const int k16 = ks << 4;
            const int arow = mw * 64 + (lane & 15);
            const int acol = k16 + ((lane >> 4) << 3);
            uint32_t ah[4][4], al[4][4], bh[4][2], bl[4][2];
            #pragma unroll
            for (int mt = 0; mt < 4; mt++) {
                uint32_t aoff = (uint32_t)((arow + mt * 16) * (32 + APAD) + acol) * 2u;
                ldsm_x4(ah[mt], sAh + aoff);
                ldsm_x4(al[mt], sAl + aoff);
            }
            const int brow = k16 + (lane & 15);
            #pragma unroll
            for (int half = 0; half < 2; half++) {
                uint32_t boff = (uint32_t)(brow * (128 + BPAD)
                              + nw * 32 + half * 16 + ((lane >> 4) << 3)) * 2u;
                uint32_t t[4];
                ldsm_x4_t(t, sBh + boff);
                bh[half*2][0] = t[0]; bh[half*2][1] = t[1];
                bh[half*2+1][0] = t[2]; bh[half*2+1][1] = t[3];
                ldsm_x4_t(t, sBl + boff);
                bl[half*2][0] = t[0]; bl[half*2][1] = t[1];
                bl[half*2+1][0] = t[2]; bl[half*2+1][1] = t[3];
            }
            #pragma unroll
            for (int mt = 0; mt < 4; mt++)
                #pragma unroll
                for (int nt = 0; nt < 4; nt++) {
                    mma16816(acc[mt][nt], ah[mt], bh[nt]);
                    mma16816(acc[mt][nt], ah[mt], bl[nt]);
                    mma16816(acc[mt][nt], al[mt], bh[nt]);
                }
        }
        __syncthreads();
    }

    // ---- epilogue ----
    #pragma unroll
    for (int mt = 0; mt < 4; mt++) {
        #pragma unroll
        for (int nt = 0; nt < 4; nt++) {
            int mrow = m0 + mw * 64 + mt * 16 + (lane >> 2);
            int col  = j0 + nw * 32 + nt * 8 + (lane & 3) * 2;
            #pragma unroll
            for (int hh = 0; hh < 2; hh++) {
                int m = mrow + hh * 8;
                float2 o;
                float vv[2] = {acc[mt][nt][hh*2], acc[mt][nt][hh*2+1]};
                #pragma unroll
                for (int q = 0; q < 2; q++) {
                    int jj = col + q;
                    float v = vv[q] + bias[jj];
                    if (GELU) {
                        float xx = v;
                        float t = fast_tanh(0.7978845608028654f * (xx + 0.044715f * xx * xx * xx));
                        v = 0.5f * xx * (1.0f + t);
                    }
                    if (RESID) {
                        float r = resid[(size_t)m * J + jj];
                        v += (r - nmean[jj]) * nrstd[jj];
                    }
                    (q == 0 ? o.x : o.y) = v;
                }
                *reinterpret_cast<float2*>(&C[(size_t)m * J + col]) = o;
            }
        }
    }
}

// ---------------------------------------------------------------------------
// Neighborhood attention: one block = 4x4x4 position tile x one head.
// ---------------------------------------------------------------------------
__global__ __launch_bounds__(64)
void nattn(const float* __restrict__ qkv, const float* __restrict__ rpb,
           float* __restrict__ out)
{
    __shared__ float Kt[216 * 16];
    __shared__ float Vt[216 * 16];
    __shared__ float Bsh[125];

    const int head = blockIdx.y;
    const int tile = blockIdx.x;
    const int th = tile >> 6, tw = (tile >> 3) & 7, tz = tile & 7;
    const int h0 = th * 4, w0 = tw * 4, z0 = tz * 4;
    const int rbh = h0 - 1, rbw = w0 - 1, rbz = z0 - 1;
    const int tid = threadIdx.x;

    for (int i = tid; i < 216 * 4; i += 64) {
        int p  = i >> 2;
        int d4 = (i & 3) * 4;
        int pz = p % 6, pw = (p / 6) % 6, ph = p / 36;
        int gh = min(max(rbh + ph, 0), 31);
        int gw = min(max(rbw + pw, 0), 31);
        int gz = min(max(rbz + pz, 0), 31);
        int n = (gh * 32 + gw) * 32 + gz;
        const float* base = qkv + (size_t)n * 384 + head * 16 + d4;
        *reinterpret_cast<float4*>(&Kt[p * 16 + d4]) = *reinterpret_cast<const float4*>(base + 128);
        *reinterpret_cast<float4*>(&Vt[p * 16 + d4]) = *reinterpret_cast<const float4*>(base + 256);
    }
    for (int i = tid; i < 125; i += 64) Bsh[i] = rpb[head * 125 + i];
    __syncthreads();

    const int lz = tid & 3, lw = (tid >> 2) & 3, lh = tid >> 4;
    const int qh = h0 + lh, qw = w0 + lw, qz = z0 + lz;
    const int n = (qh * 32 + qw) * 32 + qz;

    float q[16];
    {
        const float4* qp = reinterpret_cast<const float4*>(qkv + (size_t)n * 384 + head * 16);
        #pragma unroll
        for (int d4 = 0; d4 < 4; d4++) {
            float4 v = qp[d4];
            q[d4*4+0] = v.x * 0.25f; q[d4*4+1] = v.y * 0.25f;
            q[d4*4+2] = v.z * 0.25f; q[d4*4+3] = v.w * 0.25f;
        }
    }

    const int sh = min(max(qh - 1, 0), 29);
    const int sw = min(max(qw - 1, 0), 29);
    const int sz = min(max(qz - 1, 0), 29);

    float logits[27];
    float mx = -1e30f;
    #pragma unroll
    for (int ii = 0; ii < 27; ii++) {
        int iz = ii % 3, iw = (ii / 3) % 3, ih = ii / 9;
        int nh = sh + ih, nw_ = sw + iw, nz = sz + iz;
        int sp = ((nh - rbh) * 6 + (nw_ - rbw)) * 6 + (nz - rbz);
        const float4* kp = reinterpret_cast<const float4*>(&Kt[sp * 16]);
        float dot = 0.f;
        #pragma unroll
        for (int d4 = 0; d4 < 4; d4++) {
            float4 kv = kp[d4];
            dot += q[d4*4+0]*kv.x + q[d4*4+1]*kv.y + q[d4*4+2]*kv.z + q[d4*4+3]*kv.w;
        }
        int rh = nh - qh + 2, rw = nw_ - qw + 2, rz = nz - qz + 2;
        dot += Bsh[(rh * 5 + rw) * 5 + rz];
        logits[ii] = dot;
        mx = fmaxf(mx, dot);
    }
    float s = 0.f;
    #pragma unroll
    for (int ii = 0; ii < 27; ii++) { logits[ii] = __expf(logits[ii] - mx); s += logits[ii]; }
    const float inv = 1.0f / s;

    float o[16] = {};
    #pragma unroll
    for (int ii = 0; ii < 27; ii++) {
        int iz = ii % 3, iw = (ii / 3) % 3, ih = ii / 9;
        int sp = ((sh + ih - rbh) * 6 + (sw + iw - rbw)) * 6 + (sz + iz - rbz);
        const float4* vp = reinterpret_cast<const float4*>(&Vt[sp * 16]);
        float w = logits[ii];
        #pragma unroll
        for (int d4 = 0; d4 < 4; d4++) {
            float4 vv = vp[d4];
            o[d4*4+0] += w * vv.x; o[d4*4+1] += w * vv.y;
            o[d4*4+2] += w * vv.z; o[d4*4+3] += w * vv.w;
        }
    }
    float4* op = reinterpret_cast<float4*>(out + (size_t)n * 128 + head * 16);
    #pragma unroll
    for (int d4 = 0; d4 < 4; d4++) {
        float4 v;
        v.x = o[d4*4+0]*inv; v.y = o[d4*4+1]*inv;
        v.z = o[d4*4+2]*inv; v.w = o[d4*4+3]*inv;
        op[d4] = v;
    }
}

// ---------------------------------------------------------------------------
// Instance-norm statistics over N per channel (y is [N,128] row-major)
// ---------------------------------------------------------------------------
__global__ void zero_stats(float* s) { s[threadIdx.x] = 0.f; }   // 256 threads

__global__ __launch_bounds__(128)
void stats_kernel(const float* __restrict__ y, float* __restrict__ sum,
                  float* __restrict__ sumsq)
{
    const int c = threadIdx.x;
    const int r0 = blockIdx.x * 256;
    float s = 0.f, s2 = 0.f;
    #pragma unroll 4
    for (int r = 0; r < 256; r++) {
        float v = y[(size_t)(r0 + r) * 128 + c];
        s += v; s2 += v * v;
    }
    atomicAdd(&sum[c], s);
    atomicAdd(&sumsq[c], s2);
}

__global__ void finalize_stats(const float* sum, const float* sumsq,
                               float* mean, float* rstd)
{
    int c = threadIdx.x;
    float m = sum[c] * (1.0f / NPOS);
    mean[c] = m;
    rstd[c] = rsqrtf(sumsq[c] * (1.0f / NPOS) - m * m + 1e-5f);
}

// ---------------------------------------------------------------------------
// Final: normalize + transpose [N,128] -> [128,N]
// ---------------------------------------------------------------------------
__global__ __launch_bounds__(256)
void transnorm(const float* __restrict__ y, const float* __restrict__ mean,
               const float* __restrict__ rstd, float* __restrict__ out)
{
    __shared__ float tile[32][33];
    const int n0 = blockIdx.x * 32;
    const int c0 = blockIdx.y * 32;
    const int tx = threadIdx.x, ty = threadIdx.y;
    for (int i = ty; i < 32; i += 8)
        tile[i][tx] = y[(size_t)(n0 + i) * 128 + c0 + tx];
    __syncthreads();
    for (int i = ty; i < 32; i += 8) {
        int c = c0 + i;
        out[(size_t)c * NPOS + n0 + tx] = (tile[tx][i] - mean[c]) * rstd[c];
    }
}

// ---------------------------------------------------------------------------
// Launch
// ---------------------------------------------------------------------------
extern "C" void kernel_launch(void* const* d_in, const int* in_sizes, int n_in,
                              void* d_out, int out_size)
{
    const float* x      = (const float*)d_in[0];
    const float* w_qkv  = (const float*)d_in[1];
    const float* b_qkv  = (const float*)d_in[2];
    const float* rpb    = (const float*)d_in[3];
    const float* w_proj = (const float*)d_in[4];
    const float* b_proj = (const float*)d_in[5];
    const float* w_ffn1 = (const float*)d_in[6];
    const float* b_ffn1 = (const float*)d_in[7];
    const float* w_ffn2 = (const float*)d_in[8];
    const float* b_ffn2 = (const float*)d_in[9];
    float* out = (float*)d_out;

    float *qkv, *attno, *proj, *ffn1, *y, *st;
    cudaGetSymbolAddress((void**)&qkv,   g_qkv);
    cudaGetSymbolAddress((void**)&attno, g_attno);
    cudaGetSymbolAddress((void**)&proj,  g_proj);
    cudaGetSymbolAddress((void**)&ffn1,  g_ffn1);
    cudaGetSymbolAddress((void**)&y,     g_y);
    cudaGetSymbolAddress((void**)&st,    g_stats);

    // 1. QKV GEMM: A = x^T (x stored [128, N])
    mmagemm<true,false,false,false><<<dim3(3, 256), 256>>>(
        x, w_qkv, b_qkv, nullptr, nullptr, nullptr, qkv, NPOS, 384, 128);

    // 2. neighborhood attention
    nattn<<<dim3(512, NHEADS), 64>>>(qkv, rpb, attno);

    // 3. proj GEMM
    mmagemm<false,false,false,false><<<dim3(1, 256), 256>>>(
        attno, w_proj, b_proj, nullptr, nullptr, nullptr, proj, NPOS, 128, 128);

    // 4. instance norm #1 stats (of proj)
    zero_stats<<<1, 256>>>(st);
    stats_kernel<<<128, 128>>>(proj, st, st + 128);
    finalize_stats<<<1, 128>>>(st, st + 128, st + 256, st + 384);

    // 5. FFN1 (A = normalized proj) + gelu
    mmagemm<false,true,true,false><<<dim3(4, 256), 256>>>(
        proj, w_ffn1, b_ffn1, st + 256, st + 384, nullptr, ffn1, NPOS, 512, 128);

    // 6. FFN2 + residual (residual = normalized proj)
    mmagemm<false,false,false,true><<<dim3(1, 256), 256>>>(
        ffn1, w_ffn2, b_ffn2, st + 256, st + 384, proj, y, NPOS, 128, 512);

    // 7. instance norm #2 stats (of y)
    zero_stats<<<1, 256>>>(st);
    stats_kernel<<<128, 128>>>(y, st, st + 128);
    finalize_stats<<<1, 128>>>(st, st + 128, st + 256, st + 384);

    // 8. normalize + transpose to [C, N]
    transnorm<<<dim3(1024, 4), dim3(32, 8)>>>(y, st + 256, st + 384, out);
}